// round 5
// baseline (speedup 1.0000x reference)
#include <cuda_runtime.h>
#include <cuda_bf16.h>

#define NB 16
#define HH 512
#define WW 512
#define PLANE (HH * WW)
#define TOTAL (NB * PLANE)

// Padded layout: 516 rows x 520 cols. Data at rows 1..512, cols 4..515.
// Guard cells are zero from module load and NEVER written -> stay zero forever.
// Gather coords clamped to [-1,512]; clamped/out-of-range corners read zero
// guard cells or carry zero weight == zeros-padding grid_sample semantics.
#define SP 520
#define SROWS 516
#define PP (SROWS * SP)
#define POFF(y, x) (((y) + 1) * SP + ((x) + 4))

__device__ float2 g_dispA[NB * PP];
__device__ float2 g_dispB[NB * PP];
__device__ float  g_ldA[NB * PP];
__device__ float  g_ldB[NB * PP];

__device__ __forceinline__ float2 bilin2(const float2* __restrict__ plane, float sy, float sx) {
    sy = fminf(fmaxf(sy, -1.f), 512.f);
    sx = fminf(fmaxf(sx, -1.f), 512.f);
    float fy0 = floorf(sy), fx0 = floorf(sx);
    float wy = sy - fy0, wx = sx - fx0;
    int y0 = (int)fy0, x0 = (int)fx0;
    int base = POFF(y0, x0);
    float2 v00 = plane[base];
    float2 v01 = plane[base + 1];
    float2 v10 = plane[base + SP];
    float2 v11 = plane[base + SP + 1];
    float w00 = (1.f - wx) * (1.f - wy);
    float w01 = wx * (1.f - wy);
    float w10 = (1.f - wx) * wy;
    float w11 = wx * wy;
    return make_float2(v00.x * w00 + v01.x * w01 + v10.x * w10 + v11.x * w11,
                       v00.y * w00 + v01.y * w01 + v10.y * w10 + v11.y * w11);
}

__device__ __forceinline__ float bilin1(const float* __restrict__ plane, float sy, float sx) {
    sy = fminf(fmaxf(sy, -1.f), 512.f);
    sx = fminf(fmaxf(sx, -1.f), 512.f);
    float fy0 = floorf(sy), fx0 = floorf(sx);
    float wy = sy - fy0, wx = sx - fx0;
    int y0 = (int)fy0, x0 = (int)fx0;
    int base = POFF(y0, x0);
    float v00 = plane[base];
    float v01 = plane[base + 1];
    float v10 = plane[base + SP];
    float v11 = plane[base + SP + 1];
    float w00 = (1.f - wx) * (1.f - wy);
    float w01 = wx * (1.f - wy);
    float w10 = (1.f - wx) * wy;
    float w11 = wx * wy;
    return v00 * w00 + v01 * w01 + v10 * w10 + v11 * w11;
}

// logdet(I + eps*J) 4-term trace series via power-sum recurrence.
__device__ __forceinline__ float logdet_series(float J00, float J01, float J10, float J11) {
    const float eps = 0.0078125f;  // 2^-7
    float t = J00 + J11;
    float d = J00 * J11 - J01 * J10;
    float s2 = t * t - 2.f * d;
    float s3 = t * s2 - d * t;
    float s4 = t * s3 - d * s2;
    const float e2 = eps * eps, e3 = e2 * eps, e4 = e3 * eps;
    return eps * t - 0.5f * e2 * s2 + (e3 * (1.f / 3.f)) * s3 - 0.25f * e4 * s4;
}

// Init (4 pixels/thread): disp0 = eps*vel, ldjac0 from Sobel Jacobian.
// Shared 6-column window per thread; float4 center loads.
__global__ void __launch_bounds__(256) init_kernel(const float* __restrict__ vel) {
    int tid = blockIdx.x * blockDim.x + threadIdx.x;
    if (tid >= TOTAL / 4) return;
    int idx = tid << 2;
    int n = idx >> 18;            // / PLANE
    int rem = idx & (PLANE - 1);
    int y = rem >> 9;
    int x = rem & (WW - 1);       // multiple of 4

    const float* v0 = vel + (size_t)(2 * n) * PLANE;
    const float* v1 = v0 + PLANE;

    const float eps = 0.0078125f;

    int ym = max(y - 1, 0), yp = min(y + 1, HH - 1);
    int rmo = ym * WW, rco = y * WW, rpo = yp * WW;
    int xl = max(x - 1, 0), xr = min(x + 4, WW - 1);

    // 6-col windows: w[0]=x-1 .. w[5]=x+4 (clamped at edges)
    float am[6], ac[6], ap[6], bm[6], bc[6], bp[6];
    {
        float4 t;
        am[0] = v0[rmo + xl]; t = *(const float4*)(v0 + rmo + x); am[1]=t.x; am[2]=t.y; am[3]=t.z; am[4]=t.w; am[5] = v0[rmo + xr];
        ac[0] = v0[rco + xl]; t = *(const float4*)(v0 + rco + x); ac[1]=t.x; ac[2]=t.y; ac[3]=t.z; ac[4]=t.w; ac[5] = v0[rco + xr];
        ap[0] = v0[rpo + xl]; t = *(const float4*)(v0 + rpo + x); ap[1]=t.x; ap[2]=t.y; ap[3]=t.z; ap[4]=t.w; ap[5] = v0[rpo + xr];
        bm[0] = v1[rmo + xl]; t = *(const float4*)(v1 + rmo + x); bm[1]=t.x; bm[2]=t.y; bm[3]=t.z; bm[4]=t.w; bm[5] = v1[rmo + xr];
        bc[0] = v1[rco + xl]; t = *(const float4*)(v1 + rco + x); bc[1]=t.x; bc[2]=t.y; bc[3]=t.z; bc[4]=t.w; bc[5] = v1[rco + xr];
        bp[0] = v1[rpo + xl]; t = *(const float4*)(v1 + rpo + x); bp[1]=t.x; bp[2]=t.y; bp[3]=t.z; bp[4]=t.w; bp[5] = v1[rpo + xr];
    }

    int po = n * PP + POFF(y, x);
    *(float4*)(g_dispA + po)     = make_float4(eps * ac[1], eps * bc[1], eps * ac[2], eps * bc[2]);
    *(float4*)(g_dispA + po + 2) = make_float4(eps * ac[3], eps * bc[3], eps * ac[4], eps * bc[4]);

    float ld[4];
#pragma unroll
    for (int j = 0; j < 4; j++) {
        float J00 = 0.125f * ((ap[j] + 2.f * ap[j+1] + ap[j+2]) - (am[j] + 2.f * am[j+1] + am[j+2]));
        float J01 = 0.125f * ((am[j+2] + 2.f * ac[j+2] + ap[j+2]) - (am[j] + 2.f * ac[j] + ap[j]));
        float J10 = 0.125f * ((bp[j] + 2.f * bp[j+1] + bp[j+2]) - (bm[j] + 2.f * bm[j+1] + bm[j+2]));
        float J11 = 0.125f * ((bm[j+2] + 2.f * bc[j+2] + bp[j+2]) - (bm[j] + 2.f * bc[j] + bp[j]));
        ld[j] = logdet_series(J00, J01, J10, J11);
    }
    *(float4*)(g_ldA + po) = make_float4(ld[0], ld[1], ld[2], ld[3]);
}

// One squaring step, fused, 4 pixels/thread:
//   disp_new = disp_old + warp(disp_old, disp_old)
//   ldjac_new = ldjac_old + warp(ldjac_old, disp_new)
template <bool SRC_A, bool FINAL>
__global__ void __launch_bounds__(256) step_kernel(float* __restrict__ out_disp,
                                                   float* __restrict__ out_ld) {
    int tid = blockIdx.x * blockDim.x + threadIdx.x;
    if (tid >= TOTAL / 4) return;
    int idx = tid << 2;
    int n = idx >> 18;
    int rem = idx & (PLANE - 1);
    int y = rem >> 9;
    int x = rem & (WW - 1);   // multiple of 4

    const float2* __restrict__ dp = (SRC_A ? g_dispA : g_dispB) + (size_t)n * PP;
    const float*  __restrict__ lp = (SRC_A ? g_ldA   : g_ldB)   + (size_t)n * PP;

    const float SC = (float)HH / (float)(HH - 1);

    int po = POFF(y, x);
    float4 dc01 = *(const float4*)(dp + po);       // px0 (x,y), px1 (z,w)
    float4 dc23 = *(const float4*)(dp + po + 2);   // px2, px3
    float4 lc   = *(const float4*)(lp + po);

    float fy = (float)y, fx = (float)x;

    float d0x = dc01.x, d0y = dc01.y, d1x = dc01.z, d1y = dc01.w;
    float d2x = dc23.x, d2y = dc23.y, d3x = dc23.z, d3y = dc23.w;

    float2 s0 = bilin2(dp, (fy + d0x) * SC - 0.5f, (fx       + d0y) * SC - 0.5f);
    float2 s1 = bilin2(dp, (fy + d1x) * SC - 0.5f, (fx + 1.f + d1y) * SC - 0.5f);
    float2 s2 = bilin2(dp, (fy + d2x) * SC - 0.5f, (fx + 2.f + d2y) * SC - 0.5f);
    float2 s3 = bilin2(dp, (fy + d3x) * SC - 0.5f, (fx + 3.f + d3y) * SC - 0.5f);

    float dn0x = d0x + s0.x, dn0y = d0y + s0.y;
    float dn1x = d1x + s1.x, dn1y = d1y + s1.y;
    float dn2x = d2x + s2.x, dn2y = d2y + s2.y;
    float dn3x = d3x + s3.x, dn3y = d3y + s3.y;

    float l0 = lc.x + bilin1(lp, (fy + dn0x) * SC - 0.5f, (fx       + dn0y) * SC - 0.5f);
    float l1 = lc.y + bilin1(lp, (fy + dn1x) * SC - 0.5f, (fx + 1.f + dn1y) * SC - 0.5f);
    float l2 = lc.z + bilin1(lp, (fy + dn2x) * SC - 0.5f, (fx + 2.f + dn2y) * SC - 0.5f);
    float l3 = lc.w + bilin1(lp, (fy + dn3x) * SC - 0.5f, (fx + 3.f + dn3y) * SC - 0.5f);

    if (FINAL) {
        // planar output: disp [N,2,H,W] then ldjac [N,1,H,W]
        *(float4*)(out_disp + (size_t)(2 * n) * PLANE + rem)     = make_float4(dn0x, dn1x, dn2x, dn3x);
        *(float4*)(out_disp + (size_t)(2 * n + 1) * PLANE + rem) = make_float4(dn0y, dn1y, dn2y, dn3y);
        *(float4*)(out_ld + (size_t)n * PLANE + rem)             = make_float4(l0, l1, l2, l3);
    } else {
        float2* __restrict__ ddst = (SRC_A ? g_dispB : g_dispA) + (size_t)n * PP;
        float*  __restrict__ ldst = (SRC_A ? g_ldB   : g_ldA)   + (size_t)n * PP;
        *(float4*)(ddst + po)     = make_float4(dn0x, dn0y, dn1x, dn1y);
        *(float4*)(ddst + po + 2) = make_float4(dn2x, dn2y, dn3x, dn3y);
        *(float4*)(ldst + po)     = make_float4(l0, l1, l2, l3);
    }
}

extern "C" void kernel_launch(void* const* d_in, const int* in_sizes, int n_in,
                              void* d_out, int out_size) {
    const float* vel = (const float*)d_in[0];
    float* out = (float*)d_out;
    float* out_disp = out;
    float* out_ld = out + (size_t)NB * 2 * PLANE;

    const int threads = 256;
    const int blocks = (TOTAL / 4 + threads - 1) / threads;

    init_kernel<<<blocks, threads>>>(vel);
    // 7 steps: A->B, B->A, A->B, B->A, A->B, B->A, A->out
    step_kernel<true,  false><<<blocks, threads>>>(out_disp, out_ld);
    step_kernel<false, false><<<blocks, threads>>>(out_disp, out_ld);
    step_kernel<true,  false><<<blocks, threads>>>(out_disp, out_ld);
    step_kernel<false, false><<<blocks, threads>>>(out_disp, out_ld);
    step_kernel<true,  false><<<blocks, threads>>>(out_disp, out_ld);
    step_kernel<false, false><<<blocks, threads>>>(out_disp, out_ld);
    step_kernel<true,  true ><<<blocks, threads>>>(out_disp, out_ld);
}

// round 7
// speedup vs baseline: 1.4187x; 1.4187x over previous
#include <cuda_runtime.h>
#include <cuda_bf16.h>

#define NB 16
#define HH 512
#define WW 512
#define PLANE (HH * WW)
#define TOTAL (NB * PLANE)

// Padded layout: 516 rows x 520 cols. Data at rows 1..512, cols 4..515.
// Guard cells are zero from module load and NEVER written -> stay zero forever.
// Gather coords clamped to [-1,512]; clamped/out-of-range corners read zero
// guard cells or carry zero weight == zeros-padding grid_sample semantics.
#define SP 520
#define SROWS 516
#define PP (SROWS * SP)
#define POFF(y, x) (((y) + 1) * SP + ((x) + 4))

__device__ float2 g_dispA[NB * PP];
__device__ float2 g_dispB[NB * PP];
__device__ float  g_ldA[NB * PP];
__device__ float  g_ldB[NB * PP];

__device__ __forceinline__ float2 bilin2(const float2* __restrict__ plane, float sy, float sx) {
    sy = fminf(fmaxf(sy, -1.f), 512.f);
    sx = fminf(fmaxf(sx, -1.f), 512.f);
    float fy0 = floorf(sy), fx0 = floorf(sx);
    float wy = sy - fy0, wx = sx - fx0;
    int y0 = (int)fy0, x0 = (int)fx0;
    int base = POFF(y0, x0);
    float2 v00 = plane[base];
    float2 v01 = plane[base + 1];
    float2 v10 = plane[base + SP];
    float2 v11 = plane[base + SP + 1];
    float w00 = (1.f - wx) * (1.f - wy);
    float w01 = wx * (1.f - wy);
    float w10 = (1.f - wx) * wy;
    float w11 = wx * wy;
    return make_float2(v00.x * w00 + v01.x * w01 + v10.x * w10 + v11.x * w11,
                       v00.y * w00 + v01.y * w01 + v10.y * w10 + v11.y * w11);
}

__device__ __forceinline__ float bilin1(const float* __restrict__ plane, float sy, float sx) {
    sy = fminf(fmaxf(sy, -1.f), 512.f);
    sx = fminf(fmaxf(sx, -1.f), 512.f);
    float fy0 = floorf(sy), fx0 = floorf(sx);
    float wy = sy - fy0, wx = sx - fx0;
    int y0 = (int)fy0, x0 = (int)fx0;
    int base = POFF(y0, x0);
    float v00 = plane[base];
    float v01 = plane[base + 1];
    float v10 = plane[base + SP];
    float v11 = plane[base + SP + 1];
    float w00 = (1.f - wx) * (1.f - wy);
    float w01 = wx * (1.f - wy);
    float w10 = (1.f - wx) * wy;
    float w11 = wx * wy;
    return v00 * w00 + v01 * w01 + v10 * w10 + v11 * w11;
}

// logdet(I + eps*J) 4-term trace series via power-sum recurrence.
__device__ __forceinline__ float logdet_series(float J00, float J01, float J10, float J11) {
    const float eps = 0.0078125f;  // 2^-7
    float t = J00 + J11;
    float d = J00 * J11 - J01 * J10;
    float s2 = t * t - 2.f * d;
    float s3 = t * s2 - d * t;
    float s4 = t * s3 - d * s2;
    const float e2 = eps * eps, e3 = e2 * eps, e4 = e3 * eps;
    return eps * t - 0.5f * e2 * s2 + (e3 * (1.f / 3.f)) * s3 - 0.25f * e4 * s4;
}

// Init (4 pixels/thread): disp0 = eps*vel, ldjac0 from Sobel Jacobian.
__global__ void __launch_bounds__(256) init_kernel(const float* __restrict__ vel) {
    int tid = blockIdx.x * blockDim.x + threadIdx.x;
    if (tid >= TOTAL / 4) return;
    int idx = tid << 2;
    int n = idx >> 18;            // / PLANE
    int rem = idx & (PLANE - 1);
    int y = rem >> 9;
    int x = rem & (WW - 1);       // multiple of 4

    const float* v0 = vel + (size_t)(2 * n) * PLANE;
    const float* v1 = v0 + PLANE;

    const float eps = 0.0078125f;

    int ym = max(y - 1, 0), yp = min(y + 1, HH - 1);
    int rmo = ym * WW, rco = y * WW, rpo = yp * WW;
    int xl = max(x - 1, 0), xr = min(x + 4, WW - 1);

    // 6-col windows: w[0]=x-1 .. w[5]=x+4 (clamped at edges)
    float am[6], ac[6], ap[6], bm[6], bc[6], bp[6];
    {
        float4 t;
        am[0] = v0[rmo + xl]; t = *(const float4*)(v0 + rmo + x); am[1]=t.x; am[2]=t.y; am[3]=t.z; am[4]=t.w; am[5] = v0[rmo + xr];
        ac[0] = v0[rco + xl]; t = *(const float4*)(v0 + rco + x); ac[1]=t.x; ac[2]=t.y; ac[3]=t.z; ac[4]=t.w; ac[5] = v0[rco + xr];
        ap[0] = v0[rpo + xl]; t = *(const float4*)(v0 + rpo + x); ap[1]=t.x; ap[2]=t.y; ap[3]=t.z; ap[4]=t.w; ap[5] = v0[rpo + xr];
        bm[0] = v1[rmo + xl]; t = *(const float4*)(v1 + rmo + x); bm[1]=t.x; bm[2]=t.y; bm[3]=t.z; bm[4]=t.w; bm[5] = v1[rmo + xr];
        bc[0] = v1[rco + xl]; t = *(const float4*)(v1 + rco + x); bc[1]=t.x; bc[2]=t.y; bc[3]=t.z; bc[4]=t.w; bc[5] = v1[rco + xr];
        bp[0] = v1[rpo + xl]; t = *(const float4*)(v1 + rpo + x); bp[1]=t.x; bp[2]=t.y; bp[3]=t.z; bp[4]=t.w; bp[5] = v1[rpo + xr];
    }

    int po = n * PP + POFF(y, x);
    *(float4*)(g_dispA + po)     = make_float4(eps * ac[1], eps * bc[1], eps * ac[2], eps * bc[2]);
    *(float4*)(g_dispA + po + 2) = make_float4(eps * ac[3], eps * bc[3], eps * ac[4], eps * bc[4]);

    float ld[4];
#pragma unroll
    for (int j = 0; j < 4; j++) {
        float J00 = 0.125f * ((ap[j] + 2.f * ap[j+1] + ap[j+2]) - (am[j] + 2.f * am[j+1] + am[j+2]));
        float J01 = 0.125f * ((am[j+2] + 2.f * ac[j+2] + ap[j+2]) - (am[j] + 2.f * ac[j] + ap[j]));
        float J10 = 0.125f * ((bp[j] + 2.f * bp[j+1] + bp[j+2]) - (bm[j] + 2.f * bm[j+1] + bm[j+2]));
        float J11 = 0.125f * ((bm[j+2] + 2.f * bc[j+2] + bp[j+2]) - (bm[j] + 2.f * bc[j] + bp[j]));
        ld[j] = logdet_series(J00, J01, J10, J11);
    }
    *(float4*)(g_ldA + po) = make_float4(ld[0], ld[1], ld[2], ld[3]);
}

// One squaring step, fused, 2 pixels/thread, 2D-tiled blocks:
// block = 128 cols x 4 rows (256 threads, warp = 64 contiguous px in one row).
// Gather source rows are reused ~4x within one SM's L1.
template <bool SRC_A, bool FINAL>
__global__ void __launch_bounds__(256) step_kernel(float* __restrict__ out_disp,
                                                   float* __restrict__ out_ld) {
    int bx = blockIdx.x;
    int n  = bx >> 9;            // 512 tiles per image (4 col-tiles * 128 row-tiles)
    int t  = bx & 511;
    int ty = t >> 2;             // 0..127 (row tile of 4 rows)
    int tx = t & 3;              // 0..3   (col tile of 128 px)
    int r  = threadIdx.x >> 6;   // 0..3 row within tile
    int c  = threadIdx.x & 63;   // 0..63 col pair
    int y  = (ty << 2) + r;
    int x  = (tx << 7) + (c << 1);   // even

    const float2* __restrict__ dp = (SRC_A ? g_dispA : g_dispB) + (size_t)n * PP;
    const float*  __restrict__ lp = (SRC_A ? g_ldA   : g_ldB)   + (size_t)n * PP;

    const float SC = (float)HH / (float)(HH - 1);

    int po = POFF(y, x);
    float4 dc = *(const float4*)(dp + po);   // px0=(dc.x,dc.y), px1=(dc.z,dc.w)
    float2 lc = *(const float2*)(lp + po);

    float fy = (float)y, fx = (float)x;
    float sy0 = (fy + dc.x) * SC - 0.5f;
    float sx0 = (fx + dc.y) * SC - 0.5f;
    float sy1 = (fy + dc.z) * SC - 0.5f;
    float sx1 = (fx + 1.f + dc.w) * SC - 0.5f;

    float2 s0 = bilin2(dp, sy0, sx0);
    float2 s1 = bilin2(dp, sy1, sx1);

    float dn0x = dc.x + s0.x, dn0y = dc.y + s0.y;
    float dn1x = dc.z + s1.x, dn1y = dc.w + s1.y;

    float l0 = lc.x + bilin1(lp, (fy + dn0x) * SC - 0.5f, (fx + dn0y) * SC - 0.5f);
    float l1 = lc.y + bilin1(lp, (fy + dn1x) * SC - 0.5f, (fx + 1.f + dn1y) * SC - 0.5f);

    if (FINAL) {
        int rem = (y << 9) + x;
        // planar output: disp [N,2,H,W] then ldjac [N,1,H,W]
        *(float2*)(out_disp + (size_t)(2 * n) * PLANE + rem)     = make_float2(dn0x, dn1x);
        *(float2*)(out_disp + (size_t)(2 * n + 1) * PLANE + rem) = make_float2(dn0y, dn1y);
        *(float2*)(out_ld + (size_t)n * PLANE + rem)             = make_float2(l0, l1);
    } else {
        float2* __restrict__ ddst = (SRC_A ? g_dispB : g_dispA) + (size_t)n * PP;
        float*  __restrict__ ldst = (SRC_A ? g_ldB   : g_ldA)   + (size_t)n * PP;
        *(float4*)(ddst + po) = make_float4(dn0x, dn0y, dn1x, dn1y);
        *(float2*)(ldst + po) = make_float2(l0, l1);
    }
}

extern "C" void kernel_launch(void* const* d_in, const int* in_sizes, int n_in,
                              void* d_out, int out_size) {
    const float* vel = (const float*)d_in[0];
    float* out = (float*)d_out;
    float* out_disp = out;
    float* out_ld = out + (size_t)NB * 2 * PLANE;

    const int threads = 256;
    const int init_blocks = (TOTAL / 4 + threads - 1) / threads;
    const int step_blocks = NB * 512;   // 4 col-tiles * 128 row-tiles per image

    init_kernel<<<init_blocks, threads>>>(vel);
    // 7 steps: A->B, B->A, A->B, B->A, A->B, B->A, A->out
    step_kernel<true,  false><<<step_blocks, threads>>>(out_disp, out_ld);
    step_kernel<false, false><<<step_blocks, threads>>>(out_disp, out_ld);
    step_kernel<true,  false><<<step_blocks, threads>>>(out_disp, out_ld);
    step_kernel<false, false><<<step_blocks, threads>>>(out_disp, out_ld);
    step_kernel<true,  false><<<step_blocks, threads>>>(out_disp, out_ld);
    step_kernel<false, false><<<step_blocks, threads>>>(out_disp, out_ld);
    step_kernel<true,  true ><<<step_blocks, threads>>>(out_disp, out_ld);
}

// round 8
// speedup vs baseline: 1.5604x; 1.0999x over previous
#include <cuda_runtime.h>
#include <cuda_bf16.h>

#define NB 16
#define HH 512
#define WW 512
#define PLANE (HH * WW)
#define TOTAL (NB * PLANE)

// Padded layout: 516 rows x 520 cols. Data at rows 1..512, cols 4..515.
// Guard cells are zero from module load and NEVER written -> stay zero forever.
// Gather coords clamped to [-1,512]; clamped/out-of-range corners read zero
// guard cells or carry zero weight == zeros-padding grid_sample semantics.
#define SP 520
#define SROWS 516
#define PP (SROWS * SP)
#define POFF(y, x) (((y) + 1) * SP + ((x) + 4))

__device__ float2 g_dispA[NB * PP];
__device__ float2 g_dispB[NB * PP];
__device__ float  g_ldA[NB * PP];
__device__ float  g_ldB[NB * PP];

__device__ __forceinline__ float2 bilin2(const float2* __restrict__ plane, float sy, float sx) {
    sy = fminf(fmaxf(sy, -1.f), 512.f);
    sx = fminf(fmaxf(sx, -1.f), 512.f);
    float fy0 = floorf(sy), fx0 = floorf(sx);
    float wy = sy - fy0, wx = sx - fx0;
    int y0 = (int)fy0, x0 = (int)fx0;
    int base = POFF(y0, x0);
    float2 v00 = plane[base];
    float2 v01 = plane[base + 1];
    float2 v10 = plane[base + SP];
    float2 v11 = plane[base + SP + 1];
    float w00 = (1.f - wx) * (1.f - wy);
    float w01 = wx * (1.f - wy);
    float w10 = (1.f - wx) * wy;
    float w11 = wx * wy;
    return make_float2(v00.x * w00 + v01.x * w01 + v10.x * w10 + v11.x * w11,
                       v00.y * w00 + v01.y * w01 + v10.y * w10 + v11.y * w11);
}

__device__ __forceinline__ float bilin1(const float* __restrict__ plane, float sy, float sx) {
    sy = fminf(fmaxf(sy, -1.f), 512.f);
    sx = fminf(fmaxf(sx, -1.f), 512.f);
    float fy0 = floorf(sy), fx0 = floorf(sx);
    float wy = sy - fy0, wx = sx - fx0;
    int y0 = (int)fy0, x0 = (int)fx0;
    int base = POFF(y0, x0);
    float v00 = plane[base];
    float v01 = plane[base + 1];
    float v10 = plane[base + SP];
    float v11 = plane[base + SP + 1];
    float w00 = (1.f - wx) * (1.f - wy);
    float w01 = wx * (1.f - wy);
    float w10 = (1.f - wx) * wy;
    float w11 = wx * wy;
    return v00 * w00 + v01 * w01 + v10 * w10 + v11 * w11;
}

// logdet(I + eps*J) 4-term trace series via power-sum recurrence.
__device__ __forceinline__ float logdet_series(float J00, float J01, float J10, float J11) {
    const float eps = 0.0078125f;  // 2^-7
    float t = J00 + J11;
    float d = J00 * J11 - J01 * J10;
    float s2 = t * t - 2.f * d;
    float s3 = t * s2 - d * t;
    float s4 = t * s3 - d * s2;
    const float e2 = eps * eps, e3 = e2 * eps, e4 = e3 * eps;
    return eps * t - 0.5f * e2 * s2 + (e3 * (1.f / 3.f)) * s3 - 0.25f * e4 * s4;
}

// Init (4 pixels/thread): disp0 = eps*vel, ldjac0 from Sobel Jacobian.
__global__ void __launch_bounds__(256) init_kernel(const float* __restrict__ vel) {
    int tid = blockIdx.x * blockDim.x + threadIdx.x;
    if (tid >= TOTAL / 4) return;
    int idx = tid << 2;
    int n = idx >> 18;            // / PLANE
    int rem = idx & (PLANE - 1);
    int y = rem >> 9;
    int x = rem & (WW - 1);       // multiple of 4

    const float* v0 = vel + (size_t)(2 * n) * PLANE;
    const float* v1 = v0 + PLANE;

    const float eps = 0.0078125f;

    int ym = max(y - 1, 0), yp = min(y + 1, HH - 1);
    int rmo = ym * WW, rco = y * WW, rpo = yp * WW;
    int xl = max(x - 1, 0), xr = min(x + 4, WW - 1);

    // 6-col windows: w[0]=x-1 .. w[5]=x+4 (clamped at edges)
    float am[6], ac[6], ap[6], bm[6], bc[6], bp[6];
    {
        float4 t;
        am[0] = v0[rmo + xl]; t = *(const float4*)(v0 + rmo + x); am[1]=t.x; am[2]=t.y; am[3]=t.z; am[4]=t.w; am[5] = v0[rmo + xr];
        ac[0] = v0[rco + xl]; t = *(const float4*)(v0 + rco + x); ac[1]=t.x; ac[2]=t.y; ac[3]=t.z; ac[4]=t.w; ac[5] = v0[rco + xr];
        ap[0] = v0[rpo + xl]; t = *(const float4*)(v0 + rpo + x); ap[1]=t.x; ap[2]=t.y; ap[3]=t.z; ap[4]=t.w; ap[5] = v0[rpo + xr];
        bm[0] = v1[rmo + xl]; t = *(const float4*)(v1 + rmo + x); bm[1]=t.x; bm[2]=t.y; bm[3]=t.z; bm[4]=t.w; bm[5] = v1[rmo + xr];
        bc[0] = v1[rco + xl]; t = *(const float4*)(v1 + rco + x); bc[1]=t.x; bc[2]=t.y; bc[3]=t.z; bc[4]=t.w; bc[5] = v1[rco + xr];
        bp[0] = v1[rpo + xl]; t = *(const float4*)(v1 + rpo + x); bp[1]=t.x; bp[2]=t.y; bp[3]=t.z; bp[4]=t.w; bp[5] = v1[rpo + xr];
    }

    int po = n * PP + POFF(y, x);
    *(float4*)(g_dispA + po)     = make_float4(eps * ac[1], eps * bc[1], eps * ac[2], eps * bc[2]);
    *(float4*)(g_dispA + po + 2) = make_float4(eps * ac[3], eps * bc[3], eps * ac[4], eps * bc[4]);

    float ld[4];
#pragma unroll
    for (int j = 0; j < 4; j++) {
        float J00 = 0.125f * ((ap[j] + 2.f * ap[j+1] + ap[j+2]) - (am[j] + 2.f * am[j+1] + am[j+2]));
        float J01 = 0.125f * ((am[j+2] + 2.f * ac[j+2] + ap[j+2]) - (am[j] + 2.f * ac[j] + ap[j]));
        float J10 = 0.125f * ((bp[j] + 2.f * bp[j+1] + bp[j+2]) - (bm[j] + 2.f * bm[j+1] + bm[j+2]));
        float J11 = 0.125f * ((bm[j+2] + 2.f * bc[j+2] + bp[j+2]) - (bm[j] + 2.f * bc[j] + bp[j]));
        ld[j] = logdet_series(J00, J01, J10, J11);
    }
    *(float4*)(g_ldA + po) = make_float4(ld[0], ld[1], ld[2], ld[3]);
}

// One squaring step, fused, 2 VERTICALLY adjacent pixels/thread.
// Warp = 32 contiguous columns x 2 rows -> scattered gather instructions span
// only ~32px*8B ~ 2-3 cache lines each (half the wavefronts of the horizontal
// pairing). Block = 32 cols x 16 rows (256 threads).
template <bool SRC_A, bool FINAL>
__global__ void __launch_bounds__(256) step_kernel(float* __restrict__ out_disp,
                                                   float* __restrict__ out_ld) {
    int bx = blockIdx.x;
    int n  = bx >> 9;            // 512 tiles per image (16 col-tiles * 32 row-tiles)
    int t  = bx & 511;
    int tx = t & 15;             // 0..15 col tile (32 cols)
    int ty = t >> 4;             // 0..31 row tile (16 rows)
    int lane = threadIdx.x & 31;
    int w    = threadIdx.x >> 5; // 0..7 row-pair within tile
    int x = (tx << 5) + lane;
    int y = (ty << 4) + (w << 1);   // rows y, y+1

    const float2* __restrict__ dp = (SRC_A ? g_dispA : g_dispB) + (size_t)n * PP;
    const float*  __restrict__ lp = (SRC_A ? g_ldA   : g_ldB)   + (size_t)n * PP;

    const float SC = (float)HH / (float)(HH - 1);

    int po0 = POFF(y, x);
    int po1 = po0 + SP;
    float2 d0 = dp[po0];
    float2 d1 = dp[po1];
    float lc0 = lp[po0];
    float lc1 = lp[po1];

    float fy = (float)y, fx = (float)x;
    float2 s0 = bilin2(dp, (fy       + d0.x) * SC - 0.5f, (fx + d0.y) * SC - 0.5f);
    float2 s1 = bilin2(dp, (fy + 1.f + d1.x) * SC - 0.5f, (fx + d1.y) * SC - 0.5f);

    float dn0x = d0.x + s0.x, dn0y = d0.y + s0.y;
    float dn1x = d1.x + s1.x, dn1y = d1.y + s1.y;

    float l0 = lc0 + bilin1(lp, (fy       + dn0x) * SC - 0.5f, (fx + dn0y) * SC - 0.5f);
    float l1 = lc1 + bilin1(lp, (fy + 1.f + dn1x) * SC - 0.5f, (fx + dn1y) * SC - 0.5f);

    if (FINAL) {
        int rem0 = (y << 9) + x;
        int rem1 = rem0 + WW;
        float* od0 = out_disp + (size_t)(2 * n) * PLANE;      // channel 0 plane
        float* od1 = out_disp + (size_t)(2 * n + 1) * PLANE;  // channel 1 plane
        float* ol  = out_ld   + (size_t)n * PLANE;
        od0[rem0] = dn0x; od0[rem1] = dn1x;
        od1[rem0] = dn0y; od1[rem1] = dn1y;
        ol[rem0]  = l0;   ol[rem1]  = l1;
    } else {
        float2* __restrict__ ddst = (SRC_A ? g_dispB : g_dispA) + (size_t)n * PP;
        float*  __restrict__ ldst = (SRC_A ? g_ldB   : g_ldA)   + (size_t)n * PP;
        ddst[po0] = make_float2(dn0x, dn0y);
        ddst[po1] = make_float2(dn1x, dn1y);
        ldst[po0] = l0;
        ldst[po1] = l1;
    }
}

extern "C" void kernel_launch(void* const* d_in, const int* in_sizes, int n_in,
                              void* d_out, int out_size) {
    const float* vel = (const float*)d_in[0];
    float* out = (float*)d_out;
    float* out_disp = out;
    float* out_ld = out + (size_t)NB * 2 * PLANE;

    const int threads = 256;
    const int init_blocks = (TOTAL / 4 + threads - 1) / threads;
    const int step_blocks = NB * 512;   // 16 col-tiles * 32 row-tiles per image

    init_kernel<<<init_blocks, threads>>>(vel);
    // 7 steps: A->B, B->A, A->B, B->A, A->B, B->A, A->out
    step_kernel<true,  false><<<step_blocks, threads>>>(out_disp, out_ld);
    step_kernel<false, false><<<step_blocks, threads>>>(out_disp, out_ld);
    step_kernel<true,  false><<<step_blocks, threads>>>(out_disp, out_ld);
    step_kernel<false, false><<<step_blocks, threads>>>(out_disp, out_ld);
    step_kernel<true,  false><<<step_blocks, threads>>>(out_disp, out_ld);
    step_kernel<false, false><<<step_blocks, threads>>>(out_disp, out_ld);
    step_kernel<true,  true ><<<step_blocks, threads>>>(out_disp, out_ld);
}